// round 5
// baseline (speedup 1.0000x reference)
#include <cuda_runtime.h>
#include <cstdint>
#include <cstddef>

// Problem dims (fixed by the dataset)
#define M_DIM 8192
#define N_DIM 4096
#define K_DIM 4096

#define BM 128
#define BN 128
#define BK 32
#define STAGES 3
#define A_BYTES (BM * BK * 4)                 // 16384
#define STAGE_BYTES (2 * A_BYTES)             // 32768 (A tile + B tile)
#define SMEM_BYTES (STAGES * STAGE_BYTES)     // 98304

// Scratch (allocation-free rule: __device__ globals)
__device__ float g_Wp[(size_t)N_DIM * K_DIM];     // W + 2*B@A, tf32-rounded  (64 MB)
__device__ float g_Xp[(size_t)M_DIM * K_DIM];     // x, tf32-rounded          (128 MB)
__device__ float g_biasp[N_DIM];                  // bias + 2*delta_bias

// ---------------------------------------------------------------------------
// helpers
// ---------------------------------------------------------------------------
__device__ __forceinline__ float tf32_rn(float x) {
    uint32_t u;
    asm volatile("cvt.rna.tf32.f32 %0, %1;\n" : "=r"(u) : "f"(x));
    return __uint_as_float(u);
}

__device__ __forceinline__ void cp16(uint32_t smem_dst, const void* gmem_ptr) {
    asm volatile("cp.async.cg.shared.global [%0], [%1], 16;\n"
                 :: "r"(smem_dst), "l"(gmem_ptr));
}

__device__ __forceinline__ void ldsm4(uint32_t& r0, uint32_t& r1, uint32_t& r2, uint32_t& r3,
                                      uint32_t saddr) {
    asm volatile("ldmatrix.sync.aligned.m8n8.x4.shared.b16 {%0,%1,%2,%3}, [%4];\n"
                 : "=r"(r0), "=r"(r1), "=r"(r2), "=r"(r3) : "r"(saddr));
}

__device__ __forceinline__ void mma_tf32(float* d, const uint32_t* a, uint32_t b0, uint32_t b1) {
    asm volatile(
        "mma.sync.aligned.m16n8k8.row.col.f32.tf32.tf32.f32 "
        "{%0,%1,%2,%3},{%4,%5,%6,%7},{%8,%9},{%0,%1,%2,%3};\n"
        : "+f"(d[0]), "+f"(d[1]), "+f"(d[2]), "+f"(d[3])
        : "r"(a[0]), "r"(a[1]), "r"(a[2]), "r"(a[3]), "r"(b0), "r"(b1));
}

// ---------------------------------------------------------------------------
// prep kernels
// ---------------------------------------------------------------------------

// W' = tf32_rn(W + 2 * B @ A)     W:[N,K], B:[N,16], A:[16,K]
__global__ void prep_w(const float* __restrict__ W,
                       const float* __restrict__ B,
                       const float* __restrict__ A) {
    __shared__ float As[16][128];
    __shared__ float Bs[16][16];
    const int k0 = blockIdx.x * 128;
    const int n0 = blockIdx.y * 16;
    const int tid = threadIdx.x;

    for (int i = tid; i < 16 * 128; i += 256) {
        int r = i >> 7, kk = i & 127;
        As[r][kk] = A[(size_t)r * K_DIM + k0 + kk];
    }
    {
        int nn = tid >> 4, r = tid & 15;
        Bs[nn][r] = B[(size_t)(n0 + nn) * 16 + r];
    }
    __syncthreads();

    #pragma unroll
    for (int it = 0; it < 2; ++it) {
        int u = tid + it * 256;
        int nn = u >> 5;          // local n row (0..15)
        int gg = u & 31;          // float4 granule within 128 k's
        int n = n0 + nn;
        int k = k0 + gg * 4;
        float4 w = *reinterpret_cast<const float4*>(W + (size_t)n * K_DIM + k);
        float a0 = 0.f, a1 = 0.f, a2 = 0.f, a3 = 0.f;
        int kl = gg * 4;
        #pragma unroll
        for (int r = 0; r < 16; ++r) {
            float b = Bs[nn][r];
            a0 += b * As[r][kl];
            a1 += b * As[r][kl + 1];
            a2 += b * As[r][kl + 2];
            a3 += b * As[r][kl + 3];
        }
        w.x = tf32_rn(w.x + 2.0f * a0);
        w.y = tf32_rn(w.y + 2.0f * a1);
        w.z = tf32_rn(w.z + 2.0f * a2);
        w.w = tf32_rn(w.w + 2.0f * a3);
        *reinterpret_cast<float4*>(g_Wp + (size_t)n * K_DIM + k) = w;
    }
}

// Xp = tf32_rn(x)
__global__ void prep_x(const float* __restrict__ x) {
    size_t i = (size_t)blockIdx.x * 256 + threadIdx.x;   // float4 index
    float4 v = ((const float4*)x)[i];
    v.x = tf32_rn(v.x); v.y = tf32_rn(v.y);
    v.z = tf32_rn(v.z); v.w = tf32_rn(v.w);
    ((float4*)g_Xp)[i] = v;
}

// bias' = bias + 2*delta_bias
__global__ void prep_bias(const float* __restrict__ bias, const float* __restrict__ db) {
    int i = blockIdx.x * 256 + threadIdx.x;
    if (i < N_DIM) g_biasp[i] = bias[i] + 2.0f * db[i];
}

// ---------------------------------------------------------------------------
// main GEMM: out[M,N] = Xp[M,K] @ Wp[N,K]^T + bias'
// 256 threads, 8 warps of 32x64, fetch interleaved into k-steps
// ---------------------------------------------------------------------------
__global__ __launch_bounds__(256, 2) void gemm_tf32(float* __restrict__ out) {
    extern __shared__ float smem_f[];
    const uint32_t sbase = (uint32_t)__cvta_generic_to_shared(smem_f);
    const int tid   = threadIdx.x;
    const int lane  = tid & 31;
    const int warp  = tid >> 5;
    const int warpM = warp & 3;   // 4 warps over M (4*32 = 128)
    const int warpN = warp >> 2;  // 2 warps over N (2*64 = 128)
    const int bN = blockIdx.x;
    const int bM = blockIdx.y;

    float acc[2][8][4];
    #pragma unroll
    for (int i = 0; i < 2; ++i)
        #pragma unroll
        for (int j = 0; j < 8; ++j)
            #pragma unroll
            for (int k = 0; k < 4; ++k) acc[i][j][k] = 0.f;

    // --- per-thread constant cp.async geometry ---
    // granule u = tid + s*256  ->  g = tid&7 (const), m_s = (tid>>3) + 32*s,
    // slot = g ^ ((tid>>3)&7) (const since 32*s ≡ 0 mod 8)
    const uint32_t cp_g    = (uint32_t)(tid & 7);
    const uint32_t cp_m0   = (uint32_t)(tid >> 3);
    const uint32_t cp_slot = cp_g ^ (cp_m0 & 7);
    const uint32_t cp_dstA0 = cp_m0 * 128 + cp_slot * 16;            // + s*4096
    const uint32_t cp_dstB0 = A_BYTES + cp_dstA0;
    const float* cp_srcA0 = g_Xp + (size_t)(bM * BM + cp_m0) * K_DIM + cp_g * 4;
    const float* cp_srcB0 = g_Wp + (size_t)(bN * BN + cp_m0) * K_DIM + cp_g * 4;
    const size_t cp_src_s = (size_t)32 * K_DIM;                       // per k-step row advance

    // ldsm base offsets within a stage; per k-step s address = base ^ (s<<5)
    const uint32_t aoff0 = (uint32_t)(warpM * 32 + (lane & 15)) * 128
                         + ((uint32_t)((lane >> 4) ^ (lane & 7)) << 4);
    const uint32_t boff0 = A_BYTES
                         + (uint32_t)(warpN * 64 + (lane & 7) + ((lane >> 4) << 3)) * 128
                         + ((uint32_t)(((lane >> 3) & 1) ^ (lane & 7)) << 4);

    const int KT = K_DIM / BK;   // 128

    // prologue: fully load stages 0,1
    #pragma unroll
    for (int st = 0; st < STAGES - 1; ++st) {
        const uint32_t d = sbase + st * STAGE_BYTES;
        const float* sA = cp_srcA0 + (size_t)st * BK;
        const float* sB = cp_srcB0 + (size_t)st * BK;
        #pragma unroll
        for (int s = 0; s < 4; ++s) {
            cp16(d + cp_dstA0 + s * 4096, sA + s * cp_src_s);
            cp16(d + cp_dstB0 + s * 4096, sB + s * cp_src_s);
        }
        asm volatile("cp.async.commit_group;\n" ::: "memory");
    }

    for (int kt = 0; kt < KT; ++kt) {
        asm volatile("cp.async.wait_group 1;\n" ::: "memory");
        __syncthreads();

        const int fetch = kt + STAGES - 1;
        const bool do_fetch = fetch < KT;
        const uint32_t fstg = sbase + (fetch % STAGES) * STAGE_BYTES;
        const float* fA = cp_srcA0 + (size_t)fetch * BK;
        const float* fB = cp_srcB0 + (size_t)fetch * BK;

        const uint32_t stg = sbase + (kt % STAGES) * STAGE_BYTES;
        const uint32_t aB = stg + aoff0;
        const uint32_t bB = stg + boff0;

        #pragma unroll
        for (int s = 0; s < 4; ++s) {   // 4 k-steps of 8 per BK=32
            const uint32_t sx = (uint32_t)(s << 5);
            uint32_t af[2][4];
            #pragma unroll
            for (int mi = 0; mi < 2; ++mi)
                ldsm4(af[mi][0], af[mi][1], af[mi][2], af[mi][3],
                      (aB + mi * 2048) ^ sx);
            uint32_t bf[4][4];
            #pragma unroll
            for (int p = 0; p < 4; ++p)
                ldsm4(bf[p][0], bf[p][1], bf[p][2], bf[p][3],
                      (bB + p * 2048) ^ sx);

            // interleaved fetch: 2 cp.async per thread per k-step
            if (do_fetch) {
                cp16(fstg + cp_dstA0 + s * 4096, fA + s * cp_src_s);
                cp16(fstg + cp_dstB0 + s * 4096, fB + s * cp_src_s);
            }

            #pragma unroll
            for (int mi = 0; mi < 2; ++mi)
                #pragma unroll
                for (int p = 0; p < 4; ++p) {
                    mma_tf32(acc[mi][2 * p],     af[mi], bf[p][0], bf[p][1]);
                    mma_tf32(acc[mi][2 * p + 1], af[mi], bf[p][2], bf[p][3]);
                }
        }
        asm volatile("cp.async.commit_group;\n" ::: "memory");
    }

    // epilogue: add bias', store float2
    const int row0 = bM * BM + warpM * 32 + (lane >> 2);
    const int col0 = bN * BN + warpN * 64 + (lane & 3) * 2;
    #pragma unroll
    for (int mi = 0; mi < 2; ++mi) {
        #pragma unroll
        for (int ni = 0; ni < 8; ++ni) {
            int c = col0 + ni * 8;
            float b0 = g_biasp[c], b1 = g_biasp[c + 1];
            #pragma unroll
            for (int h = 0; h < 2; ++h) {
                int r = row0 + mi * 16 + h * 8;
                float2 v;
                v.x = acc[mi][ni][2 * h]     + b0;
                v.y = acc[mi][ni][2 * h + 1] + b1;
                *reinterpret_cast<float2*>(out + (size_t)r * N_DIM + c) = v;
            }
        }
    }
}

// ---------------------------------------------------------------------------
extern "C" void kernel_launch(void* const* d_in, const int* in_sizes, int n_in,
                              void* d_out, int out_size) {
    const float* x          = (const float*)d_in[0];
    const float* W          = (const float*)d_in[1];
    const float* bias       = (const float*)d_in[2];
    const float* B_lora     = (const float*)d_in[3];
    const float* A_lora     = (const float*)d_in[4];
    const float* delta_bias = (const float*)d_in[5];
    float* out = (float*)d_out;

    cudaFuncSetAttribute(gemm_tf32, cudaFuncAttributeMaxDynamicSharedMemorySize, SMEM_BYTES);
    cudaFuncSetAttribute(gemm_tf32, cudaFuncAttributePreferredSharedMemoryCarveout,
                         cudaSharedmemCarveoutMaxShared);

    prep_x<<<(int)(((size_t)M_DIM * K_DIM / 4) / 256), 256>>>(x);
    prep_w<<<dim3(K_DIM / 128, N_DIM / 16), 256>>>(W, B_lora, A_lora);
    prep_bias<<<(N_DIM + 255) / 256, 256>>>(bias, delta_bias);
    gemm_tf32<<<dim3(N_DIM / BN, M_DIM / BM), 256, SMEM_BYTES>>>(out);
}

// round 6
// speedup vs baseline: 1.9581x; 1.9581x over previous
#include <cuda_runtime.h>
#include <cuda_fp16.h>
#include <cstdint>
#include <cstddef>

// Problem dims (fixed by the dataset)
#define M_DIM 8192
#define N_DIM 4096
#define K_DIM 4096

#define BM 128
#define BN 128
#define BK 64                                  // 64 halves = 128 B per row
#define KT (K_DIM / BK)                        // 64 iterations
#define A_BYTES (BM * BK * 2)                  // 16384
#define STAGE_BYTES (2 * A_BYTES)              // 32768 (A tile + B tile)
#define STAGES 3
#define SMEM_BYTES (STAGES * STAGE_BYTES)      // 98304

// Scratch (allocation-free rule: __device__ globals)
__device__ __half g_Xh[(size_t)M_DIM * K_DIM];   // x  in fp16 (64 MB)
__device__ __half g_Wh[(size_t)N_DIM * K_DIM];   // W + 2*B@A in fp16 (32 MB)
__device__ float  g_biasp[N_DIM];                // bias + 2*delta_bias

// ---------------------------------------------------------------------------
// helpers
// ---------------------------------------------------------------------------
__device__ __forceinline__ void cp16(uint32_t smem_dst, const void* gmem_ptr) {
    asm volatile("cp.async.cg.shared.global [%0], [%1], 16;\n"
                 :: "r"(smem_dst), "l"(gmem_ptr));
}

__device__ __forceinline__ void ldsm4(uint32_t& r0, uint32_t& r1, uint32_t& r2, uint32_t& r3,
                                      uint32_t saddr) {
    asm volatile("ldmatrix.sync.aligned.m8n8.x4.shared.b16 {%0,%1,%2,%3}, [%4];\n"
                 : "=r"(r0), "=r"(r1), "=r"(r2), "=r"(r3) : "r"(saddr));
}

__device__ __forceinline__ void mma_f16(float* d, const uint32_t* a, uint32_t b0, uint32_t b1) {
    asm volatile(
        "mma.sync.aligned.m16n8k16.row.col.f32.f16.f16.f32 "
        "{%0,%1,%2,%3},{%4,%5,%6,%7},{%8,%9},{%0,%1,%2,%3};\n"
        : "+f"(d[0]), "+f"(d[1]), "+f"(d[2]), "+f"(d[3])
        : "r"(a[0]), "r"(a[1]), "r"(a[2]), "r"(a[3]), "r"(b0), "r"(b1));
}

// ---------------------------------------------------------------------------
// prep kernels
// ---------------------------------------------------------------------------

// W' = half(W + 2 * B @ A)     W:[N,K], B:[N,16], A:[16,K]
__global__ void prep_w(const float* __restrict__ W,
                       const float* __restrict__ B,
                       const float* __restrict__ A) {
    __shared__ float As[16][128];
    __shared__ float Bs[16][16];
    const int k0 = blockIdx.x * 128;
    const int n0 = blockIdx.y * 16;
    const int tid = threadIdx.x;

    for (int i = tid; i < 16 * 128; i += 256) {
        int r = i >> 7, kk = i & 127;
        As[r][kk] = A[(size_t)r * K_DIM + k0 + kk];
    }
    {
        int nn = tid >> 4, r = tid & 15;
        Bs[nn][r] = B[(size_t)(n0 + nn) * 16 + r];
    }
    __syncthreads();

    #pragma unroll
    for (int it = 0; it < 2; ++it) {
        int u = tid + it * 256;
        int nn = u >> 5;          // local n row (0..15)
        int gg = u & 31;          // float4 granule within 128 k's
        int n = n0 + nn;
        int k = k0 + gg * 4;
        float4 w = *reinterpret_cast<const float4*>(W + (size_t)n * K_DIM + k);
        float a0 = 0.f, a1 = 0.f, a2 = 0.f, a3 = 0.f;
        int kl = gg * 4;
        #pragma unroll
        for (int r = 0; r < 16; ++r) {
            float b = Bs[nn][r];
            a0 += b * As[r][kl];
            a1 += b * As[r][kl + 1];
            a2 += b * As[r][kl + 2];
            a3 += b * As[r][kl + 3];
        }
        __half2 h0 = __floats2half2_rn(w.x + 2.0f * a0, w.y + 2.0f * a1);
        __half2 h1 = __floats2half2_rn(w.z + 2.0f * a2, w.w + 2.0f * a3);
        __half2* dst = reinterpret_cast<__half2*>(g_Wh + (size_t)n * K_DIM + k);
        dst[0] = h0;
        dst[1] = h1;
    }
}

// Xh = half(x)
__global__ void prep_x(const float* __restrict__ x) {
    size_t i = (size_t)blockIdx.x * 256 + threadIdx.x;   // float4 index
    float4 v = ((const float4*)x)[i];
    __half2 h0 = __floats2half2_rn(v.x, v.y);
    __half2 h1 = __floats2half2_rn(v.z, v.w);
    __half2* dst = reinterpret_cast<__half2*>(g_Xh + i * 4);
    dst[0] = h0;
    dst[1] = h1;
}

// bias' = bias + 2*delta_bias
__global__ void prep_bias(const float* __restrict__ bias, const float* __restrict__ db) {
    int i = blockIdx.x * 256 + threadIdx.x;
    if (i < N_DIM) g_biasp[i] = bias[i] + 2.0f * db[i];
}

// ---------------------------------------------------------------------------
// main GEMM: out[M,N] = Xh[M,K] @ Wh[N,K]^T + bias'
// 256 threads, 8 warps of 32x64, fp16 m16n8k16
// ---------------------------------------------------------------------------
__device__ __forceinline__ void issue_stage(uint32_t sbase, int st, int kt,
                                            int bM, int bN, int tid) {
    uint32_t sA = sbase + st * STAGE_BYTES;
    uint32_t sB = sA + A_BYTES;
    const __half* gA = g_Xh + (size_t)(bM * BM) * K_DIM + (size_t)kt * BK;
    const __half* gB = g_Wh + (size_t)(bN * BN) * K_DIM + (size_t)kt * BK;
    #pragma unroll
    for (int i = 0; i < 4; ++i) {
        int u = tid + i * 256;          // 1024 16B-granules per tile
        int m = u >> 3;                 // row 0..127
        int g = u & 7;                  // granule 0..7 (8 halves each)
        int slot = g ^ (m & 7);         // XOR swizzle at 16B granularity
        cp16(sA + m * 128 + slot * 16, gA + (size_t)m * K_DIM + g * 8);
        cp16(sB + m * 128 + slot * 16, gB + (size_t)m * K_DIM + g * 8);
    }
}

__global__ __launch_bounds__(256, 2) void gemm_f16(float* __restrict__ out) {
    extern __shared__ float smem_f[];
    const uint32_t sbase = (uint32_t)__cvta_generic_to_shared(smem_f);
    const int tid   = threadIdx.x;
    const int lane  = tid & 31;
    const int warp  = tid >> 5;
    const int warpM = warp & 3;   // 4 warps over M (4*32 = 128)
    const int warpN = warp >> 2;  // 2 warps over N (2*64 = 128)
    const int bN = blockIdx.x;
    const int bM = blockIdx.y;

    float acc[2][8][4];
    #pragma unroll
    for (int i = 0; i < 2; ++i)
        #pragma unroll
        for (int j = 0; j < 8; ++j)
            #pragma unroll
            for (int k = 0; k < 4; ++k) acc[i][j][k] = 0.f;

    // ldsm base byte offsets within a stage; per k16-step s: addr = base ^ (s<<5)
    // A x4: lanes0-7 -> m0-7 (+0B), 8-15 -> m8-15 (+0B), 16-23 -> m0-7 (+16B),
    //       24-31 -> m8-15 (+16B)  => regs (a0,a1,a2,a3) of m16k16 frag.
    const uint32_t aoff0 = (uint32_t)(warpM * 32 + (lane & 15)) * 128
                         + ((uint32_t)((lane >> 4) ^ (lane & 7)) << 4);
    // B x4: lanes0-7 -> n0-7 (+0B) = b0 tile0, 8-15 -> n0-7 (+16B) = b1 tile0,
    //       16-23 -> n8-15 (+0B) = b0 tile1, 24-31 -> n8-15 (+16B) = b1 tile1.
    const uint32_t boff0 = A_BYTES
                         + (uint32_t)(warpN * 64 + (lane & 7) + ((lane >> 4) << 3)) * 128
                         + ((uint32_t)(((lane >> 3) & 1) ^ (lane & 7)) << 4);

    // prologue: stages 0,1
    #pragma unroll
    for (int s = 0; s < STAGES - 1; ++s) {
        issue_stage(sbase, s, s, bM, bN, tid);
        asm volatile("cp.async.commit_group;\n" ::: "memory");
    }

    for (int kt = 0; kt < KT; ++kt) {
        asm volatile("cp.async.wait_group 1;\n" ::: "memory");
        __syncthreads();

        const int fetch = kt + STAGES - 1;
        if (fetch < KT) issue_stage(sbase, fetch % STAGES, fetch, bM, bN, tid);
        asm volatile("cp.async.commit_group;\n" ::: "memory");

        const uint32_t stg = sbase + (kt % STAGES) * STAGE_BYTES;
        const uint32_t aB = stg + aoff0;
        const uint32_t bB = stg + boff0;

        #pragma unroll
        for (int s = 0; s < 4; ++s) {   // 4 k-steps of 16 per BK=64
            const uint32_t sx = (uint32_t)(s << 5);
            uint32_t af[2][4];
            #pragma unroll
            for (int mi = 0; mi < 2; ++mi)
                ldsm4(af[mi][0], af[mi][1], af[mi][2], af[mi][3],
                      (aB + mi * 2048) ^ sx);           // mi*16 rows * 128B
            uint32_t bf[4][4];
            #pragma unroll
            for (int p = 0; p < 4; ++p)
                ldsm4(bf[p][0], bf[p][1], bf[p][2], bf[p][3],
                      (bB + p * 2048) ^ sx);            // p*16 n-rows * 128B
            #pragma unroll
            for (int mi = 0; mi < 2; ++mi)
                #pragma unroll
                for (int p = 0; p < 4; ++p) {
                    mma_f16(acc[mi][2 * p],     af[mi], bf[p][0], bf[p][1]);
                    mma_f16(acc[mi][2 * p + 1], af[mi], bf[p][2], bf[p][3]);
                }
        }
    }

    // epilogue: add bias', store float2
    const int row0 = bM * BM + warpM * 32 + (lane >> 2);
    const int col0 = bN * BN + warpN * 64 + (lane & 3) * 2;
    #pragma unroll
    for (int mi = 0; mi < 2; ++mi) {
        #pragma unroll
        for (int ni = 0; ni < 8; ++ni) {
            int c = col0 + ni * 8;
            float b0 = g_biasp[c], b1 = g_biasp[c + 1];
            #pragma unroll
            for (int h = 0; h < 2; ++h) {
                int r = row0 + mi * 16 + h * 8;
                float2 v;
                v.x = acc[mi][ni][2 * h]     + b0;
                v.y = acc[mi][ni][2 * h + 1] + b1;
                *reinterpret_cast<float2*>(out + (size_t)r * N_DIM + c) = v;
            }
        }
    }
}

// ---------------------------------------------------------------------------
extern "C" void kernel_launch(void* const* d_in, const int* in_sizes, int n_in,
                              void* d_out, int out_size) {
    const float* x          = (const float*)d_in[0];
    const float* W          = (const float*)d_in[1];
    const float* bias       = (const float*)d_in[2];
    const float* B_lora     = (const float*)d_in[3];
    const float* A_lora     = (const float*)d_in[4];
    const float* delta_bias = (const float*)d_in[5];
    float* out = (float*)d_out;

    cudaFuncSetAttribute(gemm_f16, cudaFuncAttributeMaxDynamicSharedMemorySize, SMEM_BYTES);
    cudaFuncSetAttribute(gemm_f16, cudaFuncAttributePreferredSharedMemoryCarveout,
                         cudaSharedmemCarveoutMaxShared);

    prep_x<<<(int)(((size_t)M_DIM * K_DIM / 4) / 256), 256>>>(x);
    prep_w<<<dim3(K_DIM / 128, N_DIM / 16), 256>>>(W, B_lora, A_lora);
    prep_bias<<<(N_DIM + 255) / 256, 256>>>(bias, delta_bias);
    gemm_f16<<<dim3(N_DIM / BN, M_DIM / BM), 256, SMEM_BYTES>>>(out);
}

// round 7
// speedup vs baseline: 1.9654x; 1.0037x over previous
#include <cuda_runtime.h>
#include <cuda_fp16.h>
#include <cstdint>
#include <cstddef>

// Problem dims (fixed by the dataset)
#define M_DIM 8192
#define N_DIM 4096
#define K_DIM 4096

#define BM 128
#define BN 128
#define BK 64                                  // 64 halves = 128 B per row
#define KT (K_DIM / BK)                        // 64 iterations
#define A_BYTES (BM * BK * 2)                  // 16384
#define STAGE_BYTES (2 * A_BYTES)              // 32768 (A tile + B tile)
#define STAGES 3
#define SMEM_BYTES (STAGES * STAGE_BYTES)      // 98304

// Scratch (allocation-free rule: __device__ globals)
__device__ __half g_Xh[(size_t)M_DIM * K_DIM];   // x  in fp16 (64 MB)
__device__ __half g_Wh[(size_t)N_DIM * K_DIM];   // W + 2*B@A in fp16 (32 MB)
__device__ float  g_biasp[N_DIM];                // bias + 2*delta_bias

// ---------------------------------------------------------------------------
// helpers
// ---------------------------------------------------------------------------
__device__ __forceinline__ void cp16(uint32_t smem_dst, const void* gmem_ptr) {
    asm volatile("cp.async.cg.shared.global [%0], [%1], 16;\n"
                 :: "r"(smem_dst), "l"(gmem_ptr));
}

__device__ __forceinline__ void ldsm4(uint32_t& r0, uint32_t& r1, uint32_t& r2, uint32_t& r3,
                                      uint32_t saddr) {
    asm volatile("ldmatrix.sync.aligned.m8n8.x4.shared.b16 {%0,%1,%2,%3}, [%4];\n"
                 : "=r"(r0), "=r"(r1), "=r"(r2), "=r"(r3) : "r"(saddr));
}

__device__ __forceinline__ void mma_f16(float* d, const uint32_t* a, uint32_t b0, uint32_t b1) {
    asm volatile(
        "mma.sync.aligned.m16n8k16.row.col.f32.f16.f16.f32 "
        "{%0,%1,%2,%3},{%4,%5,%6,%7},{%8,%9},{%0,%1,%2,%3};\n"
        : "+f"(d[0]), "+f"(d[1]), "+f"(d[2]), "+f"(d[3])
        : "r"(a[0]), "r"(a[1]), "r"(a[2]), "r"(a[3]), "r"(b0), "r"(b1));
}

// ---------------------------------------------------------------------------
// prep kernels
// ---------------------------------------------------------------------------

// W' = half(W + 2 * B @ A)     W:[N,K], B:[N,16], A:[16,K]
__global__ void prep_w(const float* __restrict__ W,
                       const float* __restrict__ B,
                       const float* __restrict__ A) {
    __shared__ float As[16][128];
    __shared__ float Bs[16][16];
    const int k0 = blockIdx.x * 128;
    const int n0 = blockIdx.y * 16;
    const int tid = threadIdx.x;

    for (int i = tid; i < 16 * 128; i += 256) {
        int r = i >> 7, kk = i & 127;
        As[r][kk] = A[(size_t)r * K_DIM + k0 + kk];
    }
    {
        int nn = tid >> 4, r = tid & 15;
        Bs[nn][r] = B[(size_t)(n0 + nn) * 16 + r];
    }
    __syncthreads();

    #pragma unroll
    for (int it = 0; it < 2; ++it) {
        int u = tid + it * 256;
        int nn = u >> 5;          // local n row (0..15)
        int gg = u & 31;          // float4 granule within 128 k's
        int n = n0 + nn;
        int k = k0 + gg * 4;
        float4 w = *reinterpret_cast<const float4*>(W + (size_t)n * K_DIM + k);
        float a0 = 0.f, a1 = 0.f, a2 = 0.f, a3 = 0.f;
        int kl = gg * 4;
        #pragma unroll
        for (int r = 0; r < 16; ++r) {
            float b = Bs[nn][r];
            a0 += b * As[r][kl];
            a1 += b * As[r][kl + 1];
            a2 += b * As[r][kl + 2];
            a3 += b * As[r][kl + 3];
        }
        __half2 h0 = __floats2half2_rn(w.x + 2.0f * a0, w.y + 2.0f * a1);
        __half2 h1 = __floats2half2_rn(w.z + 2.0f * a2, w.w + 2.0f * a3);
        __half2* dst = reinterpret_cast<__half2*>(g_Wh + (size_t)n * K_DIM + k);
        dst[0] = h0;
        dst[1] = h1;
    }
}

// Xh = half(x)
__global__ void prep_x(const float* __restrict__ x) {
    size_t i = (size_t)blockIdx.x * 256 + threadIdx.x;   // float4 index
    float4 v = ((const float4*)x)[i];
    __half2 h0 = __floats2half2_rn(v.x, v.y);
    __half2 h1 = __floats2half2_rn(v.z, v.w);
    __half2* dst = reinterpret_cast<__half2*>(g_Xh + i * 4);
    dst[0] = h0;
    dst[1] = h1;
}

// bias' = bias + 2*delta_bias
__global__ void prep_bias(const float* __restrict__ bias, const float* __restrict__ db) {
    int i = blockIdx.x * 256 + threadIdx.x;
    if (i < N_DIM) g_biasp[i] = bias[i] + 2.0f * db[i];
}

// ---------------------------------------------------------------------------
// main GEMM: out[M,N] = Xh[M,K] @ Wh[N,K]^T + bias'
// 256 threads, 8 warps of 32x64, fp16 m16n8k16
// ---------------------------------------------------------------------------
__device__ __forceinline__ void issue_stage(uint32_t sbase, int st, int kt,
                                            int bM, int bN, int tid) {
    uint32_t sA = sbase + st * STAGE_BYTES;
    uint32_t sB = sA + A_BYTES;
    const __half* gA = g_Xh + (size_t)(bM * BM) * K_DIM + (size_t)kt * BK;
    const __half* gB = g_Wh + (size_t)(bN * BN) * K_DIM + (size_t)kt * BK;
    #pragma unroll
    for (int i = 0; i < 4; ++i) {
        int u = tid + i * 256;          // 1024 16B-granules per tile
        int m = u >> 3;                 // row 0..127
        int g = u & 7;                  // granule 0..7 (8 halves each)
        int slot = g ^ (m & 7);         // XOR swizzle at 16B granularity
        cp16(sA + m * 128 + slot * 16, gA + (size_t)m * K_DIM + g * 8);
        cp16(sB + m * 128 + slot * 16, gB + (size_t)m * K_DIM + g * 8);
    }
}

__global__ __launch_bounds__(256, 2) void gemm_f16(float* __restrict__ out) {
    extern __shared__ float smem_f[];
    const uint32_t sbase = (uint32_t)__cvta_generic_to_shared(smem_f);
    const int tid   = threadIdx.x;
    const int lane  = tid & 31;
    const int warp  = tid >> 5;
    const int warpM = warp & 3;   // 4 warps over M (4*32 = 128)
    const int warpN = warp >> 2;  // 2 warps over N (2*64 = 128)
    const int bN = blockIdx.x;
    const int bM = blockIdx.y;

    float acc[2][8][4];
    #pragma unroll
    for (int i = 0; i < 2; ++i)
        #pragma unroll
        for (int j = 0; j < 8; ++j)
            #pragma unroll
            for (int k = 0; k < 4; ++k) acc[i][j][k] = 0.f;

    // ldsm base byte offsets within a stage; per k16-step s: addr = base ^ (s<<5)
    // A x4: lanes0-7 -> m0-7 (+0B), 8-15 -> m8-15 (+0B), 16-23 -> m0-7 (+16B),
    //       24-31 -> m8-15 (+16B)  => regs (a0,a1,a2,a3) of m16k16 frag.
    const uint32_t aoff0 = (uint32_t)(warpM * 32 + (lane & 15)) * 128
                         + ((uint32_t)((lane >> 4) ^ (lane & 7)) << 4);
    // B x4: lanes0-7 -> n0-7 (+0B) = b0 tile0, 8-15 -> n0-7 (+16B) = b1 tile0,
    //       16-23 -> n8-15 (+0B) = b0 tile1, 24-31 -> n8-15 (+16B) = b1 tile1.
    const uint32_t boff0 = A_BYTES
                         + (uint32_t)(warpN * 64 + (lane & 7) + ((lane >> 4) << 3)) * 128
                         + ((uint32_t)(((lane >> 3) & 1) ^ (lane & 7)) << 4);

    // prologue: stages 0,1
    #pragma unroll
    for (int s = 0; s < STAGES - 1; ++s) {
        issue_stage(sbase, s, s, bM, bN, tid);
        asm volatile("cp.async.commit_group;\n" ::: "memory");
    }

    for (int kt = 0; kt < KT; ++kt) {
        asm volatile("cp.async.wait_group 1;\n" ::: "memory");
        __syncthreads();

        const int fetch = kt + STAGES - 1;
        if (fetch < KT) issue_stage(sbase, fetch % STAGES, fetch, bM, bN, tid);
        asm volatile("cp.async.commit_group;\n" ::: "memory");

        const uint32_t stg = sbase + (kt % STAGES) * STAGE_BYTES;
        const uint32_t aB = stg + aoff0;
        const uint32_t bB = stg + boff0;

        #pragma unroll
        for (int s = 0; s < 4; ++s) {   // 4 k-steps of 16 per BK=64
            const uint32_t sx = (uint32_t)(s << 5);
            uint32_t af[2][4];
            #pragma unroll
            for (int mi = 0; mi < 2; ++mi)
                ldsm4(af[mi][0], af[mi][1], af[mi][2], af[mi][3],
                      (aB + mi * 2048) ^ sx);           // mi*16 rows * 128B
            uint32_t bf[4][4];
            #pragma unroll
            for (int p = 0; p < 4; ++p)
                ldsm4(bf[p][0], bf[p][1], bf[p][2], bf[p][3],
                      (bB + p * 2048) ^ sx);            // p*16 n-rows * 128B
            #pragma unroll
            for (int mi = 0; mi < 2; ++mi)
                #pragma unroll
                for (int p = 0; p < 4; ++p) {
                    mma_f16(acc[mi][2 * p],     af[mi], bf[p][0], bf[p][1]);
                    mma_f16(acc[mi][2 * p + 1], af[mi], bf[p][2], bf[p][3]);
                }
        }
    }

    // epilogue: add bias', store float2
    const int row0 = bM * BM + warpM * 32 + (lane >> 2);
    const int col0 = bN * BN + warpN * 64 + (lane & 3) * 2;
    #pragma unroll
    for (int mi = 0; mi < 2; ++mi) {
        #pragma unroll
        for (int ni = 0; ni < 8; ++ni) {
            int c = col0 + ni * 8;
            float b0 = g_biasp[c], b1 = g_biasp[c + 1];
            #pragma unroll
            for (int h = 0; h < 2; ++h) {
                int r = row0 + mi * 16 + h * 8;
                float2 v;
                v.x = acc[mi][ni][2 * h]     + b0;
                v.y = acc[mi][ni][2 * h + 1] + b1;
                *reinterpret_cast<float2*>(out + (size_t)r * N_DIM + c) = v;
            }
        }
    }
}

// ---------------------------------------------------------------------------
extern "C" void kernel_launch(void* const* d_in, const int* in_sizes, int n_in,
                              void* d_out, int out_size) {
    const float* x          = (const float*)d_in[0];
    const float* W          = (const float*)d_in[1];
    const float* bias       = (const float*)d_in[2];
    const float* B_lora     = (const float*)d_in[3];
    const float* A_lora     = (const float*)d_in[4];
    const float* delta_bias = (const float*)d_in[5];
    float* out = (float*)d_out;

    cudaFuncSetAttribute(gemm_f16, cudaFuncAttributeMaxDynamicSharedMemorySize, SMEM_BYTES);
    cudaFuncSetAttribute(gemm_f16, cudaFuncAttributePreferredSharedMemoryCarveout,
                         cudaSharedmemCarveoutMaxShared);

    prep_x<<<(int)(((size_t)M_DIM * K_DIM / 4) / 256), 256>>>(x);
    prep_w<<<dim3(K_DIM / 128, N_DIM / 16), 256>>>(W, B_lora, A_lora);
    prep_bias<<<(N_DIM + 255) / 256, 256>>>(bias, delta_bias);
    gemm_f16<<<dim3(N_DIM / BN, M_DIM / BM), 256, SMEM_BYTES>>>(out);
}

// round 8
// speedup vs baseline: 2.0482x; 1.0421x over previous
#include <cuda_runtime.h>
#include <cuda_fp16.h>
#include <cstdint>
#include <cstddef>

// Problem dims (fixed by the dataset)
#define M_DIM 8192
#define N_DIM 4096
#define K_DIM 4096

#define BM 128
#define BN 128
#define BK 64                                  // 64 halves = 128 B per row
#define KT (K_DIM / BK)                        // 64 iterations
#define A_BLK 16384                            // 128 rows x 128 B (fp16 tile block)
#define STAGE_BYTES (2 * A_BLK)                // 32768 (A block + B block)
#define STAGES 3
#define SMEM_CTRL 1024
#define SMEM_TOTAL (SMEM_CTRL + STAGES * STAGE_BYTES)   // 99328

// Scratch (allocation-free rule: __device__ globals)
// Packed tile blocks, swizzle pre-applied:
//  g_Xh: block (mt, kt) at byte offset (mt*KT + kt)*16384 ; inside: row*128 + ((g^(row&7))<<4)
//  g_Wh: block (nt, kt) likewise.
__device__ __half g_Xh[(size_t)M_DIM * K_DIM];   // 64 MB
__device__ __half g_Wh[(size_t)N_DIM * K_DIM];   // 32 MB
__device__ float  g_biasp[N_DIM];

// ---------------------------------------------------------------------------
// helpers
// ---------------------------------------------------------------------------
__device__ __forceinline__ void ldsm4(uint32_t& r0, uint32_t& r1, uint32_t& r2, uint32_t& r3,
                                      uint32_t saddr) {
    asm volatile("ldmatrix.sync.aligned.m8n8.x4.shared.b16 {%0,%1,%2,%3}, [%4];\n"
                 : "=r"(r0), "=r"(r1), "=r"(r2), "=r"(r3) : "r"(saddr));
}

__device__ __forceinline__ void mma_f16(float* d, const uint32_t* a, uint32_t b0, uint32_t b1) {
    asm volatile(
        "mma.sync.aligned.m16n8k16.row.col.f32.f16.f16.f32 "
        "{%0,%1,%2,%3},{%4,%5,%6,%7},{%8,%9},{%0,%1,%2,%3};\n"
        : "+f"(d[0]), "+f"(d[1]), "+f"(d[2]), "+f"(d[3])
        : "r"(a[0]), "r"(a[1]), "r"(a[2]), "r"(a[3]), "r"(b0), "r"(b1));
}

__device__ __forceinline__ void mbar_init(uint32_t mbar, uint32_t count) {
    asm volatile("mbarrier.init.shared.b64 [%0], %1;" :: "r"(mbar), "r"(count) : "memory");
}

__device__ __forceinline__ void mbar_expect_tx(uint32_t mbar, uint32_t bytes) {
    asm volatile("mbarrier.arrive.expect_tx.shared.b64 _, [%0], %1;"
                 :: "r"(mbar), "r"(bytes) : "memory");
}

__device__ __forceinline__ void mbar_arrive(uint32_t mbar) {
    asm volatile("mbarrier.arrive.shared.b64 _, [%0];" :: "r"(mbar) : "memory");
}

__device__ __forceinline__ void mbar_wait(uint32_t mbar, uint32_t parity) {
    uint32_t done;
    asm volatile(
        "{\n\t.reg .pred p;\n\t"
        "mbarrier.try_wait.parity.acquire.cta.shared::cta.b64 p, [%1], %2;\n\t"
        "selp.b32 %0, 1, 0, p;\n\t}"
        : "=r"(done) : "r"(mbar), "r"(parity) : "memory");
    if (!done) {
        asm volatile(
            "{\n\t.reg .pred P1;\n\t"
            "WAIT_LOOP_%=:\n\t"
            "mbarrier.try_wait.parity.acquire.cta.shared::cta.b64 P1, [%0], %1, 0x989680;\n\t"
            "@P1 bra.uni WAIT_DONE_%=;\n\t"
            "bra.uni WAIT_LOOP_%=;\n\t"
            "WAIT_DONE_%=:\n\t}"
            :: "r"(mbar), "r"(parity) : "memory");
    }
}

__device__ __forceinline__ void bulk_g2s(uint32_t dst, const void* src, uint32_t bytes, uint32_t mbar) {
    asm volatile(
        "cp.async.bulk.shared::cta.global.mbarrier::complete_tx::bytes [%0], [%1], %2, [%3];"
        :: "r"(dst), "l"(src), "r"(bytes), "r"(mbar) : "memory");
}

// ---------------------------------------------------------------------------
// prep kernels: fold LoRA, convert fp16, repack into swizzled 16KB tile blocks
// ---------------------------------------------------------------------------

// Xh packed: thread handles one 16B granule (8 floats -> 8 halves)
__global__ void prep_x(const float* __restrict__ x) {
    size_t i = (size_t)blockIdx.x * 256 + threadIdx.x;   // granule index
    const float4* src = reinterpret_cast<const float4*>(x) + i * 2;
    float4 v0 = src[0], v1 = src[1];
    __half2 h0 = __floats2half2_rn(v0.x, v0.y);
    __half2 h1 = __floats2half2_rn(v0.z, v0.w);
    __half2 h2 = __floats2half2_rn(v1.x, v1.y);
    __half2 h3 = __floats2half2_rn(v1.z, v1.w);
    uint32_t gk = (uint32_t)(i & 511);     // 512 granules per K-row
    size_t   m  = i >> 9;
    uint32_t kt = gk >> 3;
    uint32_t g  = gk & 7;
    size_t   mt = m >> 7;
    uint32_t row = (uint32_t)(m & 127);
    size_t blk = (mt * (size_t)KT + kt) * (size_t)A_BLK;
    uint32_t off = row * 128 + ((g ^ (row & 7)) << 4);
    uint4 p;
    p.x = *reinterpret_cast<uint32_t*>(&h0);
    p.y = *reinterpret_cast<uint32_t*>(&h1);
    p.z = *reinterpret_cast<uint32_t*>(&h2);
    p.w = *reinterpret_cast<uint32_t*>(&h3);
    *reinterpret_cast<uint4*>(reinterpret_cast<char*>(g_Xh) + blk + off) = p;
}

// Wh = half(W + 2 * B @ A), packed.  W:[N,K], B:[N,16], A:[16,K]
__global__ void prep_w(const float* __restrict__ W,
                       const float* __restrict__ B,
                       const float* __restrict__ A) {
    __shared__ float As[16][128];
    __shared__ float Bs[16][16];
    const int k0 = blockIdx.x * 128;
    const int n0 = blockIdx.y * 16;
    const int tid = threadIdx.x;

    for (int i = tid; i < 16 * 128; i += 256) {
        int r = i >> 7, kk = i & 127;
        As[r][kk] = A[(size_t)r * K_DIM + k0 + kk];
    }
    {
        int nn = tid >> 4, r = tid & 15;
        Bs[nn][r] = B[(size_t)(n0 + nn) * 16 + r];
    }
    __syncthreads();

    // one 16B granule (8 k's) per thread: 16 rows x 16 granules = 256
    const int nn = tid >> 4;
    const int kg = tid & 15;
    const int n  = n0 + nn;
    const int k  = k0 + kg * 8;
    const float4* wsrc = reinterpret_cast<const float4*>(W + (size_t)n * K_DIM + k);
    float4 w0 = wsrc[0], w1 = wsrc[1];
    float a[8];
    #pragma unroll
    for (int j = 0; j < 8; ++j) a[j] = 0.f;
    const int kl = kg * 8;
    #pragma unroll
    for (int r = 0; r < 16; ++r) {
        float b = Bs[nn][r];
        #pragma unroll
        for (int j = 0; j < 8; ++j) a[j] += b * As[r][kl + j];
    }
    __half2 h0 = __floats2half2_rn(w0.x + 2.f * a[0], w0.y + 2.f * a[1]);
    __half2 h1 = __floats2half2_rn(w0.z + 2.f * a[2], w0.w + 2.f * a[3]);
    __half2 h2 = __floats2half2_rn(w1.x + 2.f * a[4], w1.y + 2.f * a[5]);
    __half2 h3 = __floats2half2_rn(w1.z + 2.f * a[6], w1.w + 2.f * a[7]);

    uint32_t nt  = (uint32_t)n >> 7;
    uint32_t row = (uint32_t)n & 127;
    uint32_t kt  = (uint32_t)k >> 6;
    uint32_t g   = ((uint32_t)k >> 3) & 7;
    size_t blk = ((size_t)nt * KT + kt) * (size_t)A_BLK;
    uint32_t off = row * 128 + ((g ^ (row & 7)) << 4);
    uint4 p;
    p.x = *reinterpret_cast<uint32_t*>(&h0);
    p.y = *reinterpret_cast<uint32_t*>(&h1);
    p.z = *reinterpret_cast<uint32_t*>(&h2);
    p.w = *reinterpret_cast<uint32_t*>(&h3);
    *reinterpret_cast<uint4*>(reinterpret_cast<char*>(g_Wh) + blk + off) = p;
}

__global__ void prep_bias(const float* __restrict__ bias, const float* __restrict__ db) {
    int i = blockIdx.x * 256 + threadIdx.x;
    if (i < N_DIM) g_biasp[i] = bias[i] + 2.0f * db[i];
}

// ---------------------------------------------------------------------------
// main GEMM: out[M,N] = Xh @ Wh^T + bias'
// 256 threads, 8 warps of 32x64, fp16 m16n8k16
// cp.async.bulk producer (thread 0) + mbarrier rings; NO CTA barrier in loop.
// ---------------------------------------------------------------------------
__global__ __launch_bounds__(256, 2) void gemm_f16(float* __restrict__ out) {
    extern __shared__ float smem_f[];
    const uint32_t sbase = (uint32_t)__cvta_generic_to_shared(smem_f);
    const int tid   = threadIdx.x;
    const int lane  = tid & 31;
    const int warp  = tid >> 5;
    const int warpM = warp & 3;   // 4 warps over M (4*32 = 128)
    const int warpN = warp >> 2;  // 2 warps over N (2*64 = 128)
    const int bN = blockIdx.x;
    const int bM = blockIdx.y;

    // barriers: full[s] at +0,8,16 ; empty[s] at +24,32,40
    const uint32_t mb_full0  = sbase;
    const uint32_t mb_empty0 = sbase + 24;

    if (tid == 0) {
        #pragma unroll
        for (int s = 0; s < STAGES; ++s) {
            mbar_init(mb_full0 + 8 * s, 1);    // completed by expect_tx + bulk bytes
            mbar_init(mb_empty0 + 8 * s, 8);   // 8 warp arrivals
        }
    }
    __syncthreads();

    const char* gAblk = reinterpret_cast<const char*>(g_Xh) + (size_t)bM * KT * A_BLK;
    const char* gBblk = reinterpret_cast<const char*>(g_Wh) + (size_t)bN * KT * A_BLK;

    // prologue: thread 0 fills stages 0..2 (kt = 0,1,2)
    if (tid == 0) {
        #pragma unroll
        for (int s = 0; s < STAGES; ++s) {
            const uint32_t st = sbase + SMEM_CTRL + s * STAGE_BYTES;
            mbar_expect_tx(mb_full0 + 8 * s, STAGE_BYTES);
            bulk_g2s(st,         gAblk + (size_t)s * A_BLK, A_BLK, mb_full0 + 8 * s);
            bulk_g2s(st + A_BLK, gBblk + (size_t)s * A_BLK, A_BLK, mb_full0 + 8 * s);
        }
    }

    float acc[2][8][4];
    #pragma unroll
    for (int i = 0; i < 2; ++i)
        #pragma unroll
        for (int j = 0; j < 8; ++j)
            #pragma unroll
            for (int k = 0; k < 4; ++k) acc[i][j][k] = 0.f;

    // ldsm base byte offsets within a stage; per k16-step s: addr = base ^ (s<<5)
    const uint32_t aoff0 = (uint32_t)(warpM * 32 + (lane & 15)) * 128
                         + ((uint32_t)((lane >> 4) ^ (lane & 7)) << 4);
    const uint32_t boff0 = A_BLK
                         + (uint32_t)(warpN * 64 + (lane & 7) + ((lane >> 4) << 3)) * 128
                         + ((uint32_t)(((lane >> 3) & 1) ^ (lane & 7)) << 4);

    int st_idx = 0;         // kt % 3
    uint32_t par = 0;       // (kt/3) & 1

    for (int kt = 0; kt < KT; ++kt) {
        const uint32_t full_s  = mb_full0  + 8 * st_idx;
        const uint32_t empty_s = mb_empty0 + 8 * st_idx;
        const uint32_t stg = sbase + SMEM_CTRL + st_idx * STAGE_BYTES;

        mbar_wait(full_s, par);     // acquire: stage data visible

        const uint32_t aB = stg + aoff0;
        const uint32_t bB = stg + boff0;

        #pragma unroll
        for (int s = 0; s < 4; ++s) {   // 4 k-steps of 16 per BK=64
            const uint32_t sx = (uint32_t)(s << 5);
            uint32_t af[2][4];
            #pragma unroll
            for (int mi = 0; mi < 2; ++mi)
                ldsm4(af[mi][0], af[mi][1], af[mi][2], af[mi][3],
                      (aB + mi * 2048) ^ sx);
            uint32_t bf[4][4];
            #pragma unroll
            for (int p = 0; p < 4; ++p)
                ldsm4(bf[p][0], bf[p][1], bf[p][2], bf[p][3],
                      (bB + p * 2048) ^ sx);
            #pragma unroll
            for (int mi = 0; mi < 2; ++mi)
                #pragma unroll
                for (int p = 0; p < 4; ++p) {
                    mma_f16(acc[mi][2 * p],     af[mi], bf[p][0], bf[p][1]);
                    mma_f16(acc[mi][2 * p + 1], af[mi], bf[p][2], bf[p][3]);
                }
        }

        if (lane == 0) mbar_arrive(empty_s);   // this warp done with stage

        // producer: refill this stage for kt+3 once all 8 warps released it
        if (tid == 0 && kt + STAGES < KT) {
            mbar_wait(empty_s, par);
            mbar_expect_tx(full_s, STAGE_BYTES);
            bulk_g2s(stg,         gAblk + (size_t)(kt + STAGES) * A_BLK, A_BLK, full_s);
            bulk_g2s(stg + A_BLK, gBblk + (size_t)(kt + STAGES) * A_BLK, A_BLK, full_s);
        }

        if (++st_idx == STAGES) { st_idx = 0; par ^= 1; }
    }

    // epilogue: add bias', store float2
    const int row0 = bM * BM + warpM * 32 + (lane >> 2);
    const int col0 = bN * BN + warpN * 64 + (lane & 3) * 2;
    #pragma unroll
    for (int mi = 0; mi < 2; ++mi) {
        #pragma unroll
        for (int ni = 0; ni < 8; ++ni) {
            int c = col0 + ni * 8;
            float b0 = g_biasp[c], b1 = g_biasp[c + 1];
            #pragma unroll
            for (int h = 0; h < 2; ++h) {
                int r = row0 + mi * 16 + h * 8;
                float2 v;
                v.x = acc[mi][ni][2 * h]     + b0;
                v.y = acc[mi][ni][2 * h + 1] + b1;
                *reinterpret_cast<float2*>(out + (size_t)r * N_DIM + c) = v;
            }
        }
    }
}

// ---------------------------------------------------------------------------
extern "C" void kernel_launch(void* const* d_in, const int* in_sizes, int n_in,
                              void* d_out, int out_size) {
    const float* x          = (const float*)d_in[0];
    const float* W          = (const float*)d_in[1];
    const float* bias       = (const float*)d_in[2];
    const float* B_lora     = (const float*)d_in[3];
    const float* A_lora     = (const float*)d_in[4];
    const float* delta_bias = (const float*)d_in[5];
    float* out = (float*)d_out;

    cudaFuncSetAttribute(gemm_f16, cudaFuncAttributeMaxDynamicSharedMemorySize, SMEM_TOTAL);
    cudaFuncSetAttribute(gemm_f16, cudaFuncAttributePreferredSharedMemoryCarveout,
                         cudaSharedmemCarveoutMaxShared);

    prep_x<<<(int)(((size_t)M_DIM * K_DIM / 8) / 256), 256>>>(x);
    prep_w<<<dim3(K_DIM / 128, N_DIM / 16), 256>>>(W, B_lora, A_lora);
    prep_bias<<<(N_DIM + 255) / 256, 256>>>(bias, delta_bias);
    gemm_f16<<<dim3(N_DIM / BN, M_DIM / BM), 256, SMEM_TOTAL>>>(out);
}

// round 9
// speedup vs baseline: 2.0762x; 1.0137x over previous
#include <cuda_runtime.h>
#include <cuda_fp16.h>
#include <cstdint>
#include <cstddef>

// Problem dims (fixed by the dataset)
#define M_DIM 8192
#define N_DIM 4096
#define K_DIM 4096

#define BM 128
#define BN 256
#define BK 64                                  // 64 halves = 128 B per row
#define KT (K_DIM / BK)                        // 64 iterations
#define A_BLK 16384                            // 128 rows x 128 B
#define B_BLK 32768                            // 256 rows x 128 B
#define STAGE_BYTES (A_BLK + B_BLK)            // 49152
#define STAGES 3
#define SMEM_CTRL 1024
#define SMEM_TOTAL (SMEM_CTRL + STAGES * STAGE_BYTES)   // 148480

// Scratch (allocation-free rule: __device__ globals)
// Packed tile blocks, swizzle pre-applied:
//  g_Xh: block (mt, kt), mt = m>>7, 16KB each: row*128 + ((g^(row&7))<<4)
//  g_Wh: block (nt, kt), nt = n>>8, 32KB each: row*128 + ((g^(row&7))<<4)
__device__ __half g_Xh[(size_t)M_DIM * K_DIM];   // 64 MB
__device__ __half g_Wh[(size_t)N_DIM * K_DIM];   // 32 MB
__device__ float  g_biasp[N_DIM];

// ---------------------------------------------------------------------------
// helpers
// ---------------------------------------------------------------------------
__device__ __forceinline__ void ldsm4(uint32_t& r0, uint32_t& r1, uint32_t& r2, uint32_t& r3,
                                      uint32_t saddr) {
    asm volatile("ldmatrix.sync.aligned.m8n8.x4.shared.b16 {%0,%1,%2,%3}, [%4];\n"
                 : "=r"(r0), "=r"(r1), "=r"(r2), "=r"(r3) : "r"(saddr));
}

__device__ __forceinline__ void mma_f16(float* d, const uint32_t* a, uint32_t b0, uint32_t b1) {
    asm volatile(
        "mma.sync.aligned.m16n8k16.row.col.f32.f16.f16.f32 "
        "{%0,%1,%2,%3},{%4,%5,%6,%7},{%8,%9},{%0,%1,%2,%3};\n"
        : "+f"(d[0]), "+f"(d[1]), "+f"(d[2]), "+f"(d[3])
        : "r"(a[0]), "r"(a[1]), "r"(a[2]), "r"(a[3]), "r"(b0), "r"(b1));
}

__device__ __forceinline__ void mbar_init(uint32_t mbar, uint32_t count) {
    asm volatile("mbarrier.init.shared.b64 [%0], %1;" :: "r"(mbar), "r"(count) : "memory");
}

__device__ __forceinline__ void mbar_expect_tx(uint32_t mbar, uint32_t bytes) {
    asm volatile("mbarrier.arrive.expect_tx.shared.b64 _, [%0], %1;"
                 :: "r"(mbar), "r"(bytes) : "memory");
}

__device__ __forceinline__ void mbar_arrive(uint32_t mbar) {
    asm volatile("mbarrier.arrive.shared.b64 _, [%0];" :: "r"(mbar) : "memory");
}

__device__ __forceinline__ void mbar_wait(uint32_t mbar, uint32_t parity) {
    uint32_t done;
    asm volatile(
        "{\n\t.reg .pred p;\n\t"
        "mbarrier.try_wait.parity.acquire.cta.shared::cta.b64 p, [%1], %2;\n\t"
        "selp.b32 %0, 1, 0, p;\n\t}"
        : "=r"(done) : "r"(mbar), "r"(parity) : "memory");
    if (!done) {
        asm volatile(
            "{\n\t.reg .pred P1;\n\t"
            "WAIT_LOOP_%=:\n\t"
            "mbarrier.try_wait.parity.acquire.cta.shared::cta.b64 P1, [%0], %1, 0x989680;\n\t"
            "@P1 bra.uni WAIT_DONE_%=;\n\t"
            "bra.uni WAIT_LOOP_%=;\n\t"
            "WAIT_DONE_%=:\n\t}"
            :: "r"(mbar), "r"(parity) : "memory");
    }
}

__device__ __forceinline__ void bulk_g2s(uint32_t dst, const void* src, uint32_t bytes, uint32_t mbar) {
    asm volatile(
        "cp.async.bulk.shared::cta.global.mbarrier::complete_tx::bytes [%0], [%1], %2, [%3];"
        :: "r"(dst), "l"(src), "r"(bytes), "r"(mbar) : "memory");
}

// ---------------------------------------------------------------------------
// prep kernels: fold LoRA, convert fp16, repack into swizzled tile blocks
// ---------------------------------------------------------------------------

// Xh packed: thread handles one 16B granule (8 floats -> 8 halves)
__global__ void prep_x(const float* __restrict__ x) {
    size_t i = (size_t)blockIdx.x * 256 + threadIdx.x;   // granule index
    const float4* src = reinterpret_cast<const float4*>(x) + i * 2;
    float4 v0 = src[0], v1 = src[1];
    __half2 h0 = __floats2half2_rn(v0.x, v0.y);
    __half2 h1 = __floats2half2_rn(v0.z, v0.w);
    __half2 h2 = __floats2half2_rn(v1.x, v1.y);
    __half2 h3 = __floats2half2_rn(v1.z, v1.w);
    uint32_t gk = (uint32_t)(i & 511);     // 512 granules per K-row
    size_t   m  = i >> 9;
    uint32_t kt = gk >> 3;
    uint32_t g  = gk & 7;
    size_t   mt = m >> 7;
    uint32_t row = (uint32_t)(m & 127);
    size_t blk = (mt * (size_t)KT + kt) * (size_t)A_BLK;
    uint32_t off = row * 128 + ((g ^ (row & 7)) << 4);
    uint4 p;
    p.x = *reinterpret_cast<uint32_t*>(&h0);
    p.y = *reinterpret_cast<uint32_t*>(&h1);
    p.z = *reinterpret_cast<uint32_t*>(&h2);
    p.w = *reinterpret_cast<uint32_t*>(&h3);
    *reinterpret_cast<uint4*>(reinterpret_cast<char*>(g_Xh) + blk + off) = p;
}

// Wh = half(W + 2 * B @ A), packed into 256-row blocks.  W:[N,K], B:[N,16], A:[16,K]
__global__ void prep_w(const float* __restrict__ W,
                       const float* __restrict__ B,
                       const float* __restrict__ A) {
    __shared__ float As[16][128];
    __shared__ float Bs[16][16];
    const int k0 = blockIdx.x * 128;
    const int n0 = blockIdx.y * 16;
    const int tid = threadIdx.x;

    for (int i = tid; i < 16 * 128; i += 256) {
        int r = i >> 7, kk = i & 127;
        As[r][kk] = A[(size_t)r * K_DIM + k0 + kk];
    }
    {
        int nn = tid >> 4, r = tid & 15;
        Bs[nn][r] = B[(size_t)(n0 + nn) * 16 + r];
    }
    __syncthreads();

    // one 16B granule (8 k's) per thread: 16 rows x 16 granules = 256
    const int nn = tid >> 4;
    const int kg = tid & 15;
    const int n  = n0 + nn;
    const int k  = k0 + kg * 8;
    const float4* wsrc = reinterpret_cast<const float4*>(W + (size_t)n * K_DIM + k);
    float4 w0 = wsrc[0], w1 = wsrc[1];
    float a[8];
    #pragma unroll
    for (int j = 0; j < 8; ++j) a[j] = 0.f;
    const int kl = kg * 8;
    #pragma unroll
    for (int r = 0; r < 16; ++r) {
        float b = Bs[nn][r];
        #pragma unroll
        for (int j = 0; j < 8; ++j) a[j] += b * As[r][kl + j];
    }
    __half2 h0 = __floats2half2_rn(w0.x + 2.f * a[0], w0.y + 2.f * a[1]);
    __half2 h1 = __floats2half2_rn(w0.z + 2.f * a[2], w0.w + 2.f * a[3]);
    __half2 h2 = __floats2half2_rn(w1.x + 2.f * a[4], w1.y + 2.f * a[5]);
    __half2 h3 = __floats2half2_rn(w1.z + 2.f * a[6], w1.w + 2.f * a[7]);

    uint32_t nt  = (uint32_t)n >> 8;          // 256-row blocks
    uint32_t row = (uint32_t)n & 255;
    uint32_t kt  = (uint32_t)k >> 6;
    uint32_t g   = ((uint32_t)k >> 3) & 7;
    size_t blk = ((size_t)nt * KT + kt) * (size_t)B_BLK;
    uint32_t off = row * 128 + ((g ^ (row & 7)) << 4);
    uint4 p;
    p.x = *reinterpret_cast<uint32_t*>(&h0);
    p.y = *reinterpret_cast<uint32_t*>(&h1);
    p.z = *reinterpret_cast<uint32_t*>(&h2);
    p.w = *reinterpret_cast<uint32_t*>(&h3);
    *reinterpret_cast<uint4*>(reinterpret_cast<char*>(g_Wh) + blk + off) = p;
}

__global__ void prep_bias(const float* __restrict__ bias, const float* __restrict__ db) {
    int i = blockIdx.x * 256 + threadIdx.x;
    if (i < N_DIM) g_biasp[i] = bias[i] + 2.0f * db[i];
}

// ---------------------------------------------------------------------------
// main GEMM: out[M,N] = Xh @ Wh^T + bias'
// 256 threads, 8 warps of 64x64 over a 128x256 CTA tile, fp16 m16n8k16
// cp.async.bulk producer (thread 0) + mbarrier rings; NO CTA barrier in loop.
// ---------------------------------------------------------------------------
__global__ __launch_bounds__(256, 1) void gemm_f16(float* __restrict__ out) {
    extern __shared__ float smem_f[];
    const uint32_t sbase = (uint32_t)__cvta_generic_to_shared(smem_f);
    const int tid   = threadIdx.x;
    const int lane  = tid & 31;
    const int warp  = tid >> 5;
    const int warpM = warp & 1;   // 2 warps over M (2*64 = 128)
    const int warpN = warp >> 1;  // 4 warps over N (4*64 = 256)
    const int bN = blockIdx.x;    // 0..15
    const int bM = blockIdx.y;    // 0..63

    // barriers: full[s] at +0,8,16 ; empty[s] at +24,32,40
    const uint32_t mb_full0  = sbase;
    const uint32_t mb_empty0 = sbase + 24;

    if (tid == 0) {
        #pragma unroll
        for (int s = 0; s < STAGES; ++s) {
            mbar_init(mb_full0 + 8 * s, 1);
            mbar_init(mb_empty0 + 8 * s, 8);   // 8 warp arrivals
        }
    }
    __syncthreads();

    const char* gAblk = reinterpret_cast<const char*>(g_Xh) + (size_t)bM * KT * A_BLK;
    const char* gBblk = reinterpret_cast<const char*>(g_Wh) + (size_t)bN * KT * B_BLK;

    // prologue: thread 0 fills stages 0..2 (kt = 0,1,2)
    if (tid == 0) {
        #pragma unroll
        for (int s = 0; s < STAGES; ++s) {
            const uint32_t st = sbase + SMEM_CTRL + s * STAGE_BYTES;
            mbar_expect_tx(mb_full0 + 8 * s, STAGE_BYTES);
            bulk_g2s(st,         gAblk + (size_t)s * A_BLK, A_BLK, mb_full0 + 8 * s);
            bulk_g2s(st + A_BLK, gBblk + (size_t)s * B_BLK, B_BLK, mb_full0 + 8 * s);
        }
    }

    float acc[4][8][4];
    #pragma unroll
    for (int i = 0; i < 4; ++i)
        #pragma unroll
        for (int j = 0; j < 8; ++j)
            #pragma unroll
            for (int k = 0; k < 4; ++k) acc[i][j][k] = 0.f;

    // ldsm base byte offsets within a stage; per k16-step s: addr = base ^ (s<<5)
    const uint32_t aoff0 = (uint32_t)(warpM * 64 + (lane & 15)) * 128
                         + ((uint32_t)((lane >> 4) ^ (lane & 7)) << 4);
    const uint32_t boff0 = A_BLK
                         + (uint32_t)(warpN * 64 + (lane & 7) + ((lane >> 4) << 3)) * 128
                         + ((uint32_t)(((lane >> 3) & 1) ^ (lane & 7)) << 4);

    int st_idx = 0;         // kt % 3
    uint32_t par = 0;       // (kt/3) & 1

    for (int kt = 0; kt < KT; ++kt) {
        const uint32_t full_s  = mb_full0  + 8 * st_idx;
        const uint32_t empty_s = mb_empty0 + 8 * st_idx;
        const uint32_t stg = sbase + SMEM_CTRL + st_idx * STAGE_BYTES;

        mbar_wait(full_s, par);     // acquire: stage data visible

        const uint32_t aB = stg + aoff0;
        const uint32_t bB = stg + boff0;

        #pragma unroll
        for (int s = 0; s < 4; ++s) {   // 4 k-steps of 16 per BK=64
            const uint32_t sx = (uint32_t)(s << 5);
            uint32_t af[4][4];
            #pragma unroll
            for (int mi = 0; mi < 4; ++mi)
                ldsm4(af[mi][0], af[mi][1], af[mi][2], af[mi][3],
                      (aB + mi * 2048) ^ sx);
            uint32_t bf[4][4];
            #pragma unroll
            for (int p = 0; p < 4; ++p)
                ldsm4(bf[p][0], bf[p][1], bf[p][2], bf[p][3],
                      (bB + p * 2048) ^ sx);
            #pragma unroll
            for (int mi = 0; mi < 4; ++mi)
                #pragma unroll
                for (int p = 0; p < 4; ++p) {
                    mma_f16(acc[mi][2 * p],     af[mi], bf[p][0], bf[p][1]);
                    mma_f16(acc[mi][2 * p + 1], af[mi], bf[p][2], bf[p][3]);
                }
        }

        if (lane == 0) mbar_arrive(empty_s);   // this warp done with stage

        // producer: refill this stage for kt+3 once all 8 warps released it
        if (tid == 0 && kt + STAGES < KT) {
            mbar_wait(empty_s, par);
            mbar_expect_tx(full_s, STAGE_BYTES);
            bulk_g2s(stg,         gAblk + (size_t)(kt + STAGES) * A_BLK, A_BLK, full_s);
            bulk_g2s(stg + A_BLK, gBblk + (size_t)(kt + STAGES) * B_BLK, B_BLK, full_s);
        }

        if (++st_idx == STAGES) { st_idx = 0; par ^= 1; }
    }

    // epilogue: add bias', store float2
    const int row0 = bM * BM + warpM * 64 + (lane >> 2);
    const int col0 = bN * BN + warpN * 64 + (lane & 3) * 2;
    #pragma unroll
    for (int mi = 0; mi < 4; ++mi) {
        #pragma unroll
        for (int ni = 0; ni < 8; ++ni) {
            int c = col0 + ni * 8;
            float b0 = g_biasp[c], b1 = g_biasp[c + 1];
            #pragma unroll
            for (int h = 0; h < 2; ++h) {
                int r = row0 + mi * 16 + h * 8;
                float2 v;
                v.x = acc[mi][ni][2 * h]     + b0;
                v.y = acc[mi][ni][2 * h + 1] + b1;
                *reinterpret_cast<float2*>(out + (size_t)r * N_DIM + c) = v;
            }
        }
    }
}

// ---------------------------------------------------------------------------
extern "C" void kernel_launch(void* const* d_in, const int* in_sizes, int n_in,
                              void* d_out, int out_size) {
    const float* x          = (const float*)d_in[0];
    const float* W          = (const float*)d_in[1];
    const float* bias       = (const float*)d_in[2];
    const float* B_lora     = (const float*)d_in[3];
    const float* A_lora     = (const float*)d_in[4];
    const float* delta_bias = (const float*)d_in[5];
    float* out = (float*)d_out;

    cudaFuncSetAttribute(gemm_f16, cudaFuncAttributeMaxDynamicSharedMemorySize, SMEM_TOTAL);
    cudaFuncSetAttribute(gemm_f16, cudaFuncAttributePreferredSharedMemoryCarveout,
                         cudaSharedmemCarveoutMaxShared);

    prep_x<<<(int)(((size_t)M_DIM * K_DIM / 8) / 256), 256>>>(x);
    prep_w<<<dim3(K_DIM / 128, N_DIM / 16), 256>>>(W, B_lora, A_lora);
    prep_bias<<<(N_DIM + 255) / 256, 256>>>(bias, delta_bias);
    gemm_f16<<<dim3(N_DIM / BN, M_DIM / BM), 256, SMEM_TOTAL>>>(out);
}

// round 10
// speedup vs baseline: 2.0801x; 1.0019x over previous
#include <cuda_runtime.h>
#include <cuda_fp16.h>
#include <cstdint>
#include <cstddef>

// Problem dims (fixed by the dataset)
#define M_DIM 8192
#define N_DIM 4096
#define K_DIM 4096

#define BM 128
#define BN 256
#define BK 64                                  // 64 halves = 128 B per row
#define KT (K_DIM / BK)                        // 64 iterations
#define A_BLK 16384                            // 128 rows x 128 B
#define B_BLK 32768                            // 256 rows x 128 B
#define STAGE_BYTES (A_BLK + B_BLK)            // 49152
#define STAGES 4
#define SMEM_CTRL 1024
#define SMEM_TOTAL (SMEM_CTRL + STAGES * STAGE_BYTES)   // 197632

// Scratch (allocation-free rule: __device__ globals)
// Packed tile blocks, swizzle pre-applied:
//  g_Xh: block (mt, kt), mt = m>>7, 16KB each: row*128 + ((g^(row&7))<<4)
//  g_Wh: block (nt, kt), nt = n>>8, 32KB each: row*128 + ((g^(row&7))<<4)
__device__ __half g_Xh[(size_t)M_DIM * K_DIM];   // 64 MB
__device__ __half g_Wh[(size_t)N_DIM * K_DIM];   // 32 MB
__device__ float  g_biasp[N_DIM];

// ---------------------------------------------------------------------------
// helpers
// ---------------------------------------------------------------------------
__device__ __forceinline__ void ldsm4(uint32_t& r0, uint32_t& r1, uint32_t& r2, uint32_t& r3,
                                      uint32_t saddr) {
    asm volatile("ldmatrix.sync.aligned.m8n8.x4.shared.b16 {%0,%1,%2,%3}, [%4];\n"
                 : "=r"(r0), "=r"(r1), "=r"(r2), "=r"(r3) : "r"(saddr));
}

__device__ __forceinline__ void mma_f16(float* d, const uint32_t* a, uint32_t b0, uint32_t b1) {
    asm volatile(
        "mma.sync.aligned.m16n8k16.row.col.f32.f16.f16.f32 "
        "{%0,%1,%2,%3},{%4,%5,%6,%7},{%8,%9},{%0,%1,%2,%3};\n"
        : "+f"(d[0]), "+f"(d[1]), "+f"(d[2]), "+f"(d[3])
        : "r"(a[0]), "r"(a[1]), "r"(a[2]), "r"(a[3]), "r"(b0), "r"(b1));
}

__device__ __forceinline__ void mbar_init(uint32_t mbar, uint32_t count) {
    asm volatile("mbarrier.init.shared.b64 [%0], %1;" :: "r"(mbar), "r"(count) : "memory");
}

__device__ __forceinline__ void mbar_expect_tx(uint32_t mbar, uint32_t bytes) {
    asm volatile("mbarrier.arrive.expect_tx.shared.b64 _, [%0], %1;"
                 :: "r"(mbar), "r"(bytes) : "memory");
}

__device__ __forceinline__ void mbar_arrive(uint32_t mbar) {
    asm volatile("mbarrier.arrive.shared.b64 _, [%0];" :: "r"(mbar) : "memory");
}

__device__ __forceinline__ void mbar_wait(uint32_t mbar, uint32_t parity) {
    uint32_t done;
    asm volatile(
        "{\n\t.reg .pred p;\n\t"
        "mbarrier.try_wait.parity.acquire.cta.shared::cta.b64 p, [%1], %2;\n\t"
        "selp.b32 %0, 1, 0, p;\n\t}"
        : "=r"(done) : "r"(mbar), "r"(parity) : "memory");
    if (!done) {
        asm volatile(
            "{\n\t.reg .pred P1;\n\t"
            "WAIT_LOOP_%=:\n\t"
            "mbarrier.try_wait.parity.acquire.cta.shared::cta.b64 P1, [%0], %1, 0x989680;\n\t"
            "@P1 bra.uni WAIT_DONE_%=;\n\t"
            "bra.uni WAIT_LOOP_%=;\n\t"
            "WAIT_DONE_%=:\n\t}"
            :: "r"(mbar), "r"(parity) : "memory");
    }
}

__device__ __forceinline__ void bulk_g2s(uint32_t dst, const void* src, uint32_t bytes, uint32_t mbar) {
    asm volatile(
        "cp.async.bulk.shared::cta.global.mbarrier::complete_tx::bytes [%0], [%1], %2, [%3];"
        :: "r"(dst), "l"(src), "r"(bytes), "r"(mbar) : "memory");
}

// ---------------------------------------------------------------------------
// fused prep kernel: X convert+pack | W fold+convert+pack | bias
// ---------------------------------------------------------------------------
#define XBLKS 4096    // 4,194,304 granules / (256 threads * 4)
#define WBLKS 8192    // (K/128) * (N/16) = 32 * 256

__global__ void prep_all(const float* __restrict__ x,
                         const float* __restrict__ W,
                         const float* __restrict__ B,
                         const float* __restrict__ A,
                         const float* __restrict__ bias,
                         const float* __restrict__ db) {
    const int bx  = blockIdx.x;
    const int tid = threadIdx.x;

    if (bx < XBLKS) {
        // ---- X: fp32 -> fp16, packed; 4 granules (16B out each) per thread
        const size_t base = (size_t)bx * 1024 + tid;
        #pragma unroll
        for (int j = 0; j < 4; ++j) {
            const size_t i = base + j * 256;
            const float4* src = reinterpret_cast<const float4*>(x) + i * 2;
            float4 v0 = src[0], v1 = src[1];
            __half2 h0 = __floats2half2_rn(v0.x, v0.y);
            __half2 h1 = __floats2half2_rn(v0.z, v0.w);
            __half2 h2 = __floats2half2_rn(v1.x, v1.y);
            __half2 h3 = __floats2half2_rn(v1.z, v1.w);
            uint32_t gk = (uint32_t)(i & 511);     // 512 granules per K-row
            size_t   m  = i >> 9;
            uint32_t kt = gk >> 3;
            uint32_t g  = gk & 7;
            size_t   mt = m >> 7;
            uint32_t row = (uint32_t)(m & 127);
            size_t blk = (mt * (size_t)KT + kt) * (size_t)A_BLK;
            uint32_t off = row * 128 + ((g ^ (row & 7)) << 4);
            uint4 p;
            p.x = *reinterpret_cast<uint32_t*>(&h0);
            p.y = *reinterpret_cast<uint32_t*>(&h1);
            p.z = *reinterpret_cast<uint32_t*>(&h2);
            p.w = *reinterpret_cast<uint32_t*>(&h3);
            *reinterpret_cast<uint4*>(reinterpret_cast<char*>(g_Xh) + blk + off) = p;
        }
    } else if (bx < XBLKS + WBLKS) {
        // ---- W: fold LoRA, convert, pack into 256-row blocks
        const int wb = bx - XBLKS;
        const int k0 = (wb & 31) * 128;
        const int n0 = (wb >> 5) * 16;

        __shared__ float As[16][128];
        __shared__ float Bs[16][16];

        for (int i = tid; i < 16 * 128; i += 256) {
            int r = i >> 7, kk = i & 127;
            As[r][kk] = A[(size_t)r * K_DIM + k0 + kk];
        }
        {
            int nn = tid >> 4, r = tid & 15;
            Bs[nn][r] = B[(size_t)(n0 + nn) * 16 + r];
        }
        __syncthreads();

        const int nn = tid >> 4;
        const int kg = tid & 15;
        const int n  = n0 + nn;
        const int k  = k0 + kg * 8;
        const float4* wsrc = reinterpret_cast<const float4*>(W + (size_t)n * K_DIM + k);
        float4 w0 = wsrc[0], w1 = wsrc[1];
        float a[8];
        #pragma unroll
        for (int j = 0; j < 8; ++j) a[j] = 0.f;
        const int kl = kg * 8;
        #pragma unroll
        for (int r = 0; r < 16; ++r) {
            float b = Bs[nn][r];
            #pragma unroll
            for (int j = 0; j < 8; ++j) a[j] += b * As[r][kl + j];
        }
        __half2 h0 = __floats2half2_rn(w0.x + 2.f * a[0], w0.y + 2.f * a[1]);
        __half2 h1 = __floats2half2_rn(w0.z + 2.f * a[2], w0.w + 2.f * a[3]);
        __half2 h2 = __floats2half2_rn(w1.x + 2.f * a[4], w1.y + 2.f * a[5]);
        __half2 h3 = __floats2half2_rn(w1.z + 2.f * a[6], w1.w + 2.f * a[7]);

        uint32_t nt  = (uint32_t)n >> 8;          // 256-row blocks
        uint32_t row = (uint32_t)n & 255;
        uint32_t kt  = (uint32_t)k >> 6;
        uint32_t g   = ((uint32_t)k >> 3) & 7;
        size_t blk = ((size_t)nt * KT + kt) * (size_t)B_BLK;
        uint32_t off = row * 128 + ((g ^ (row & 7)) << 4);
        uint4 p;
        p.x = *reinterpret_cast<uint32_t*>(&h0);
        p.y = *reinterpret_cast<uint32_t*>(&h1);
        p.z = *reinterpret_cast<uint32_t*>(&h2);
        p.w = *reinterpret_cast<uint32_t*>(&h3);
        *reinterpret_cast<uint4*>(reinterpret_cast<char*>(g_Wh) + blk + off) = p;
    } else {
        // ---- bias' = bias + 2*delta_bias
        for (int i = tid; i < N_DIM; i += 256)
            g_biasp[i] = bias[i] + 2.0f * db[i];
    }
}

// ---------------------------------------------------------------------------
// main GEMM: out[M,N] = Xh @ Wh^T + bias'
// 288 threads: warps 0-7 compute (64x64 tiles over 128x256), warp 8 = producer.
// 4-stage cp.async.bulk + mbarrier rings; no CTA barrier in the loop.
// ---------------------------------------------------------------------------
__global__ __launch_bounds__(288, 1) void gemm_f16(float* __restrict__ out) {
    extern __shared__ float smem_f[];
    const uint32_t sbase = (uint32_t)__cvta_generic_to_shared(smem_f);
    const int tid   = threadIdx.x;
    const int lane  = tid & 31;
    const int warp  = tid >> 5;
    const int bN = blockIdx.x;    // 0..15
    const int bM = blockIdx.y;    // 0..63

    // barriers: full[s] at +0..31 ; empty[s] at +32..63
    const uint32_t mb_full0  = sbase;
    const uint32_t mb_empty0 = sbase + 32;

    if (tid == 0) {
        #pragma unroll
        for (int s = 0; s < STAGES; ++s) {
            mbar_init(mb_full0 + 8 * s, 1);
            mbar_init(mb_empty0 + 8 * s, 8);   // 8 compute-warp arrivals
        }
    }
    __syncthreads();

    const char* gAblk = reinterpret_cast<const char*>(g_Xh) + (size_t)bM * KT * A_BLK;
    const char* gBblk = reinterpret_cast<const char*>(g_Wh) + (size_t)bN * KT * B_BLK;

    if (warp == 8) {
        // ---------------- producer warp ----------------
        if (lane == 0) {
            for (int kt = 0; kt < KT; ++kt) {
                const int s = kt & 3;
                const int r = kt >> 2;
                const uint32_t full_s  = mb_full0  + 8 * s;
                const uint32_t stg = sbase + SMEM_CTRL + s * STAGE_BYTES;
                if (r > 0) mbar_wait(mb_empty0 + 8 * s, (uint32_t)(r - 1) & 1);
                mbar_expect_tx(full_s, STAGE_BYTES);
                bulk_g2s(stg,         gAblk + (size_t)kt * A_BLK, A_BLK, full_s);
                bulk_g2s(stg + A_BLK, gBblk + (size_t)kt * B_BLK, B_BLK, full_s);
            }
        }
        return;
    }

    // ---------------- compute warps ----------------
    const int warpM = warp & 1;   // 2 warps over M (2*64 = 128)
    const int warpN = warp >> 1;  // 4 warps over N (4*64 = 256)

    float acc[4][8][4];
    #pragma unroll
    for (int i = 0; i < 4; ++i)
        #pragma unroll
        for (int j = 0; j < 8; ++j)
            #pragma unroll
            for (int k = 0; k < 4; ++k) acc[i][j][k] = 0.f;

    // ldsm base byte offsets within a stage; per k16-step s: addr = base ^ (s<<5)
    const uint32_t aoff0 = (uint32_t)(warpM * 64 + (lane & 15)) * 128
                         + ((uint32_t)((lane >> 4) ^ (lane & 7)) << 4);
    const uint32_t boff0 = A_BLK
                         + (uint32_t)(warpN * 64 + (lane & 7) + ((lane >> 4) << 3)) * 128
                         + ((uint32_t)(((lane >> 3) & 1) ^ (lane & 7)) << 4);

    for (int kt = 0; kt < KT; ++kt) {
        const int s_idx = kt & 3;
        const uint32_t par = (uint32_t)(kt >> 2) & 1;
        const uint32_t full_s  = mb_full0  + 8 * s_idx;
        const uint32_t empty_s = mb_empty0 + 8 * s_idx;
        const uint32_t stg = sbase + SMEM_CTRL + s_idx * STAGE_BYTES;

        mbar_wait(full_s, par);     // acquire: stage data visible

        const uint32_t aB = stg + aoff0;
        const uint32_t bB = stg + boff0;

        #pragma unroll
        for (int s = 0; s < 4; ++s) {   // 4 k-steps of 16 per BK=64
            const uint32_t sx = (uint32_t)(s << 5);
            uint32_t af[4][4];
            #pragma unroll
            for (int mi = 0; mi < 4; ++mi)
                ldsm4(af[mi][0], af[mi][1], af[mi][2], af[mi][3],
                      (aB + mi * 2048) ^ sx);
            uint32_t bf[4][4];
            #pragma unroll
            for (int p = 0; p < 4; ++p)
                ldsm4(bf[p][0], bf[p][1], bf[p][2], bf[p][3],
                      (bB + p * 2048) ^ sx);
            #pragma unroll
            for (int mi = 0; mi < 4; ++mi)
                #pragma unroll
                for (int p = 0; p < 4; ++p) {
                    mma_f16(acc[mi][2 * p],     af[mi], bf[p][0], bf[p][1]);
                    mma_f16(acc[mi][2 * p + 1], af[mi], bf[p][2], bf[p][3]);
                }
        }

        if (lane == 0) mbar_arrive(empty_s);   // this warp done with stage
    }

    // epilogue: add bias', store float2
    const int row0 = bM * BM + warpM * 64 + (lane >> 2);
    const int col0 = bN * BN + warpN * 64 + (lane & 3) * 2;
    #pragma unroll
    for (int mi = 0; mi < 4; ++mi) {
        #pragma unroll
        for (int ni = 0; ni < 8; ++ni) {
            int c = col0 + ni * 8;
            float b0 = g_biasp[c], b1 = g_biasp[c + 1];
            #pragma unroll
            for (int h = 0; h < 2; ++h) {
                int r = row0 + mi * 16 + h * 8;
                float2 v;
                v.x = acc[mi][ni][2 * h]     + b0;
                v.y = acc[mi][ni][2 * h + 1] + b1;
                *reinterpret_cast<float2*>(out + (size_t)r * N_DIM + c) = v;
            }
        }
    }
}

// ---------------------------------------------------------------------------
extern "C" void kernel_launch(void* const* d_in, const int* in_sizes, int n_in,
                              void* d_out, int out_size) {
    const float* x          = (const float*)d_in[0];
    const float* W          = (const float*)d_in[1];
    const float* bias       = (const float*)d_in[2];
    const float* B_lora     = (const float*)d_in[3];
    const float* A_lora     = (const float*)d_in[4];
    const float* delta_bias = (const float*)d_in[5];
    float* out = (float*)d_out;

    cudaFuncSetAttribute(gemm_f16, cudaFuncAttributeMaxDynamicSharedMemorySize, SMEM_TOTAL);
    cudaFuncSetAttribute(gemm_f16, cudaFuncAttributePreferredSharedMemoryCarveout,
                         cudaSharedmemCarveoutMaxShared);

    prep_all<<<XBLKS + WBLKS + 1, 256>>>(x, W, B_lora, A_lora, bias, delta_bias);
    gemm_f16<<<dim3(N_DIM / BN, M_DIM / BM), 288, SMEM_TOTAL>>>(out);
}